// round 3
// baseline (speedup 1.0000x reference)
#include <cuda_runtime.h>
#include <cuda_bf16.h>

// ---------------- problem constants ----------------
#define N_NODES 32768
#define HID     256
#define N_GRAPH 256
#define NPG     128
#define NHEAD   8
#define HDIM    32
#define N_EDGE  524288
#define BIAS_ELEMS (N_GRAPH * NHEAD * NPG * NPG)   // 33,554,432 floats

// ---------------- scratch (no allocs allowed) ----------------
__device__ float g_Q[N_NODES * HID];
__device__ float g_K[N_NODES * HID];
__device__ float g_V[N_NODES * HID];
__device__ float g_A[N_NODES * HID];           // attention output before Wo
__device__ float g_bias[BIAS_ELEMS];

// =====================================================================
// GEMM: C[M,N] = A[M,256] @ W[256,N] + bias,  M=32768, N=K=256
// 64x64 block tile, 16x16 threads, 4x4 microtile, BK=16
// =====================================================================
__global__ __launch_bounds__(256) void gemm_bias_kernel(
    const float* __restrict__ A, const float* __restrict__ W,
    const float* __restrict__ bvec, float* __restrict__ C)
{
    __shared__ float As[64][17];
    __shared__ float Bs[16][64];

    const int tid = threadIdx.x;
    const int tx = tid & 15, ty = tid >> 4;
    const int m0 = blockIdx.y * 64, n0 = blockIdx.x * 64;
    const int K = 256, N = 256;

    const int ar = tid >> 2, ac = (tid & 3) * 4;   // A-tile load coords
    const int br = tid >> 4, bc = (tid & 15) * 4;  // B-tile load coords

    float acc[4][4] = {};

    for (int k0 = 0; k0 < K; k0 += 16) {
        float4 av = *(const float4*)&A[(size_t)(m0 + ar) * K + k0 + ac];
        As[ar][ac + 0] = av.x; As[ar][ac + 1] = av.y;
        As[ar][ac + 2] = av.z; As[ar][ac + 3] = av.w;
        *(float4*)&Bs[br][bc] = *(const float4*)&W[(size_t)(k0 + br) * N + n0 + bc];
        __syncthreads();

#pragma unroll
        for (int k = 0; k < 16; k++) {
            float a0 = As[ty * 4 + 0][k];
            float a1 = As[ty * 4 + 1][k];
            float a2 = As[ty * 4 + 2][k];
            float a3 = As[ty * 4 + 3][k];
            float4 bv = *(float4*)&Bs[k][tx * 4];
            acc[0][0] += a0 * bv.x; acc[0][1] += a0 * bv.y; acc[0][2] += a0 * bv.z; acc[0][3] += a0 * bv.w;
            acc[1][0] += a1 * bv.x; acc[1][1] += a1 * bv.y; acc[1][2] += a1 * bv.z; acc[1][3] += a1 * bv.w;
            acc[2][0] += a2 * bv.x; acc[2][1] += a2 * bv.y; acc[2][2] += a2 * bv.z; acc[2][3] += a2 * bv.w;
            acc[3][0] += a3 * bv.x; acc[3][1] += a3 * bv.y; acc[3][2] += a3 * bv.z; acc[3][3] += a3 * bv.w;
        }
        __syncthreads();
    }

    float4 bb = *(const float4*)&bvec[n0 + tx * 4];
#pragma unroll
    for (int i = 0; i < 4; i++) {
        float4 out;
        out.x = acc[i][0] + bb.x; out.y = acc[i][1] + bb.y;
        out.z = acc[i][2] + bb.z; out.w = acc[i][3] + bb.w;
        *(float4*)&C[(size_t)(m0 + ty * 4 + i) * N + n0 + tx * 4] = out;
    }
}

// =====================================================================
// Zero the bias tensor (graph replay must start clean each call)
// =====================================================================
__global__ void zero_bias_kernel()
{
    int i = blockIdx.x * blockDim.x + threadIdx.x;   // exactly BIAS_ELEMS/4 threads
    ((float4*)g_bias)[i] = make_float4(0.f, 0.f, 0.f, 0.f);
}

// =====================================================================
// Edge bias scatter:
//   total[e,h] = gate_table[type[e]][h] + edge_attr[e,:] @ We[:,h] + be[h]
//   bias[eb, h, sl, dl] += total ; if sl!=dl: bias[eb, h, dl, sl] += total
// =====================================================================
__global__ __launch_bounds__(256) void edge_bias_kernel(
    const float* __restrict__ edge_attr, const int* __restrict__ edge_index,
    const int* __restrict__ gate_type, const float* __restrict__ gate_table,
    const float* __restrict__ We, const float* __restrict__ be)
{
    __shared__ float sGate[160];   // 20 x 8
    __shared__ float sWe[64];      // 8 x 8
    __shared__ float sBe[8];

    const int tid = threadIdx.x;
    if (tid < 160) sGate[tid] = gate_table[tid];
    if (tid < 64)  sWe[tid] = We[tid];
    if (tid < 8)   sBe[tid] = be[tid];
    __syncthreads();

    const int e = blockIdx.x * blockDim.x + tid;
    if (e >= N_EDGE) return;

    const int src = edge_index[e];
    const int dst = edge_index[N_EDGE + e];
    const int eb = src >> 7;          // NPG = 128
    const int sl = src & 127;
    const int dl = dst & 127;
    const int t = gate_type[e];

    float4 ea0 = *(const float4*)&edge_attr[(size_t)e * 8];
    float4 ea1 = *(const float4*)&edge_attr[(size_t)e * 8 + 4];
    float ea[8] = { ea0.x, ea0.y, ea0.z, ea0.w, ea1.x, ea1.y, ea1.z, ea1.w };

    float tot[8];
#pragma unroll
    for (int h = 0; h < 8; h++) {
        float s = sGate[t * 8 + h] + sBe[h];
#pragma unroll
        for (int f = 0; f < 8; f++) s += ea[f] * sWe[f * 8 + h];
        tot[h] = s;
    }

    const int baseF = (eb * 8) * 16384 + sl * 128 + dl;
#pragma unroll
    for (int h = 0; h < 8; h++)
        atomicAdd(&g_bias[baseF + h * 16384], tot[h]);

    if (sl != dl) {
        const int baseR = (eb * 8) * 16384 + dl * 128 + sl;
#pragma unroll
        for (int h = 0; h < 8; h++)
            atomicAdd(&g_bias[baseR + h * 16384], tot[h]);
    }
}

// =====================================================================
// Attention: one CTA per (graph b, head h).
// S = (Q Kt) * scale + bias ; P = softmax(S) ; O = P V
// smem: Q/K/V [128][33] + S [128][129]  -> 116,736 B dynamic
// =====================================================================
#define ATTN_SMEM_BYTES ((3 * 128 * 33 + 128 * 129) * 4)

__global__ __launch_bounds__(256, 1) void attn_kernel()
{
    extern __shared__ float sm[];
    float* sQ = sm;
    float* sK = sQ + 128 * 33;
    float* sV = sK + 128 * 33;
    float* sS = sV + 128 * 33;

    const int b = blockIdx.x >> 3;
    const int h = blockIdx.x & 7;
    const int tid = threadIdx.x;

    const float* Qg = g_Q + (size_t)b * NPG * HID + h * HDIM;
    const float* Kg = g_K + (size_t)b * NPG * HID + h * HDIM;
    const float* Vg = g_V + (size_t)b * NPG * HID + h * HDIM;

    // load Q, K, V tiles (coalesced: 32-thread segments per 128B row-slice)
    for (int idx = tid; idx < NPG * HDIM; idx += 256) {
        int i = idx >> 5, d = idx & 31;
        sQ[i * 33 + d] = Qg[(size_t)i * HID + d];
        sK[i * 33 + d] = Kg[(size_t)i * HID + d];
        sV[i * 33 + d] = Vg[(size_t)i * HID + d];
    }
    __syncthreads();

    // ---- scores: 16x16 threads, each computes an 8x8 block of S ----
    const int tx = tid & 15, ty = tid >> 4;
    const int r0 = ty * 8, c0 = tx * 8;
    {
        float acc[8][8] = {};
#pragma unroll
        for (int d = 0; d < 32; d++) {
            float qa[8], kb[8];
#pragma unroll
            for (int i = 0; i < 8; i++) qa[i] = sQ[(r0 + i) * 33 + d];
#pragma unroll
            for (int j = 0; j < 8; j++) kb[j] = sK[(c0 + j) * 33 + d];
#pragma unroll
            for (int i = 0; i < 8; i++)
#pragma unroll
                for (int j = 0; j < 8; j++) acc[i][j] += qa[i] * kb[j];
        }
        const float scale = 0.17677669529663689f;  // 1/sqrt(32)
#pragma unroll
        for (int i = 0; i < 8; i++)
#pragma unroll
            for (int j = 0; j < 8; j++)
                sS[(r0 + i) * 129 + c0 + j] = acc[i][j] * scale;
    }
    __syncthreads();

    // ---- add edge bias (coalesced global read) ----
    const float* bg = g_bias + (size_t)(b * 8 + h) * (NPG * NPG);
    for (int idx = tid; idx < NPG * NPG; idx += 256)
        sS[idx + (idx >> 7)] += bg[idx];
    __syncthreads();

    // ---- softmax per row: warp w handles rows 16w..16w+15 ----
    {
        const int w = tid >> 5, lane = tid & 31;
        for (int r = w * 16; r < w * 16 + 16; r++) {
            float* row = sS + r * 129;
            float v0 = row[lane], v1 = row[lane + 32], v2 = row[lane + 64], v3 = row[lane + 96];
            float m = fmaxf(fmaxf(v0, v1), fmaxf(v2, v3));
#pragma unroll
            for (int o = 16; o > 0; o >>= 1) m = fmaxf(m, __shfl_xor_sync(0xffffffffu, m, o));
            float e0 = __expf(v0 - m), e1 = __expf(v1 - m), e2 = __expf(v2 - m), e3 = __expf(v3 - m);
            float s = e0 + e1 + e2 + e3;
#pragma unroll
            for (int o = 16; o > 0; o >>= 1) s += __shfl_xor_sync(0xffffffffu, s, o);
            float inv = 1.0f / s;
            row[lane] = e0 * inv; row[lane + 32] = e1 * inv;
            row[lane + 64] = e2 * inv; row[lane + 96] = e3 * inv;
        }
    }
    __syncthreads();

    // ---- O = P @ V : thread computes rows r0..r0+7, cols tx*2, tx*2+1 ----
    {
        float o[8][2] = {};
        const int cv = tx * 2;
#pragma unroll 4
        for (int k = 0; k < 128; k++) {
            float v0 = sV[k * 33 + cv];
            float v1 = sV[k * 33 + cv + 1];
#pragma unroll
            for (int i = 0; i < 8; i++) {
                float p = sS[(r0 + i) * 129 + k];
                o[i][0] += p * v0;
                o[i][1] += p * v1;
            }
        }
        float* Og = g_A + (size_t)b * NPG * HID + h * HDIM;
#pragma unroll
        for (int i = 0; i < 8; i++) {
            float2 w2 = make_float2(o[i][0], o[i][1]);
            *(float2*)&Og[(size_t)(r0 + i) * HID + cv] = w2;
        }
    }
}

// =====================================================================
// launch
// =====================================================================
extern "C" void kernel_launch(void* const* d_in, const int* in_sizes, int n_in,
                              void* d_out, int out_size)
{
    const float* x          = (const float*)d_in[0];
    const float* edge_attr  = (const float*)d_in[1];
    const float* Wq         = (const float*)d_in[2];
    const float* bq         = (const float*)d_in[3];
    const float* Wk         = (const float*)d_in[4];
    const float* bk         = (const float*)d_in[5];
    const float* Wv         = (const float*)d_in[6];
    const float* bv         = (const float*)d_in[7];
    const float* Wo         = (const float*)d_in[8];
    const float* bo         = (const float*)d_in[9];
    const float* gate_table = (const float*)d_in[10];
    const float* We         = (const float*)d_in[11];
    const float* be         = (const float*)d_in[12];
    const int*   edge_index = (const int*)d_in[13];
    const int*   gate_type  = (const int*)d_in[14];
    float*       out        = (float*)d_out;

    float *Qp, *Kp, *Vp, *Ap;
    cudaGetSymbolAddress((void**)&Qp, g_Q);
    cudaGetSymbolAddress((void**)&Kp, g_K);
    cudaGetSymbolAddress((void**)&Vp, g_V);
    cudaGetSymbolAddress((void**)&Ap, g_A);

    cudaFuncSetAttribute(attn_kernel, cudaFuncAttributeMaxDynamicSharedMemorySize,
                         ATTN_SMEM_BYTES);

    dim3 gg(HID / 64, N_NODES / 64);   // (4, 512)

    gemm_bias_kernel<<<gg, 256>>>(x, Wq, bq, Qp);
    gemm_bias_kernel<<<gg, 256>>>(x, Wk, bk, Kp);
    gemm_bias_kernel<<<gg, 256>>>(x, Wv, bv, Vp);

    zero_bias_kernel<<<BIAS_ELEMS / 4 / 256, 256>>>();
    edge_bias_kernel<<<N_EDGE / 256, 256>>>(edge_attr, edge_index, gate_type,
                                            gate_table, We, be);

    attn_kernel<<<N_GRAPH * NHEAD, 256, ATTN_SMEM_BYTES>>>();

    gemm_bias_kernel<<<gg, 256>>>(Ap, Wo, bo, out);
}

// round 6
// speedup vs baseline: 1.6139x; 1.6139x over previous
#include <cuda_runtime.h>
#include <cuda_bf16.h>
#include <cstdint>

// ---------------- problem constants ----------------
#define N_NODES 32768
#define HID     256
#define N_GRAPH 256
#define NPG     128
#define NHEAD   8
#define HDIM    32
#define N_EDGE  524288
#define BIAS_ELEMS (N_GRAPH * NPG * NPG * NHEAD)   // 33,554,432 floats, layout [B][q][k][H]

// ---------------- scratch (no allocs allowed) ----------------
__device__ float g_Q[N_NODES * HID];
__device__ float g_K[N_NODES * HID];
__device__ float g_V[N_NODES * HID];
__device__ float g_A[N_NODES * HID];           // attention output before Wo
__device__ float g_bias[BIAS_ELEMS];

// =====================================================================
// tf32 helpers
// =====================================================================
__device__ __forceinline__ uint32_t f2tf(float x) {
    uint32_t r;
    asm("cvt.rna.tf32.f32 %0, %1;" : "=r"(r) : "f"(x));
    return r;
}

__device__ __forceinline__ void mma_tf32(float acc[4], const uint32_t a[4], const uint32_t b[2]) {
    asm volatile(
        "mma.sync.aligned.m16n8k8.row.col.f32.tf32.tf32.f32 "
        "{%0,%1,%2,%3}, {%4,%5,%6,%7}, {%8,%9}, {%0,%1,%2,%3};\n"
        : "+f"(acc[0]), "+f"(acc[1]), "+f"(acc[2]), "+f"(acc[3])
        : "r"(a[0]), "r"(a[1]), "r"(a[2]), "r"(a[3]), "r"(b[0]), "r"(b[1]));
}

// =====================================================================
// tf32 tensor-core GEMM: C[M,256] = alpha * (A[M,256] @ W[256,256] + bvec)
// CTA tile 128x64, BK=32, 8 warps (warp tile 32x32), m16n8k8 mma.
// Smem pads chosen for conflict-free fragment loads:
//   As stride 36 (mod 32 = 4):  a-frag addr ≡ 4g+t  (bijective over lanes)
//   Bs stride 72 (mod 32 = 8):  b-frag addr ≡ 8t+g  (bijective over lanes)
// =====================================================================
__global__ __launch_bounds__(256) void gemm_tf32_kernel(
    const float* __restrict__ A, const float* __restrict__ W,
    const float* __restrict__ bvec, float* __restrict__ C, float alpha)
{
    __shared__ uint32_t As[128][36];
    __shared__ uint32_t Bs[32][72];

    const int tid = threadIdx.x;
    const int lane = tid & 31, wid = tid >> 5;
    const int wm = (wid & 3) * 32, wn = (wid >> 2) * 32;
    const int g = lane >> 2, t = lane & 3;
    const int m0 = blockIdx.y * 128, n0 = blockIdx.x * 64;

    float acc[2][4][4] = {};

    for (int k0 = 0; k0 < 256; k0 += 32) {
        // load A tile 128x32 (8 float4 per row; coalesced)
#pragma unroll
        for (int i = 0; i < 4; i++) {
            int f = tid + i * 256;
            int row = f >> 3, cv = (f & 7) * 4;
            float4 v = *(const float4*)&A[(size_t)(m0 + row) * 256 + k0 + cv];
            uint4 u = make_uint4(f2tf(v.x), f2tf(v.y), f2tf(v.z), f2tf(v.w));
            *(uint4*)&As[row][cv] = u;
        }
        // load B tile 32x64
#pragma unroll
        for (int i = 0; i < 2; i++) {
            int f = tid + i * 256;
            int row = f >> 4, cv = (f & 15) * 4;
            float4 v = *(const float4*)&W[(size_t)(k0 + row) * 256 + n0 + cv];
            uint4 u = make_uint4(f2tf(v.x), f2tf(v.y), f2tf(v.z), f2tf(v.w));
            *(uint4*)&Bs[row][cv] = u;
        }
        __syncthreads();

#pragma unroll
        for (int kk = 0; kk < 32; kk += 8) {
            uint32_t af[2][4], bf[4][2];
#pragma unroll
            for (int mt = 0; mt < 2; mt++) {
                int r = wm + mt * 16 + g;
                af[mt][0] = As[r][kk + t];
                af[mt][1] = As[r + 8][kk + t];
                af[mt][2] = As[r][kk + t + 4];
                af[mt][3] = As[r + 8][kk + t + 4];
            }
#pragma unroll
            for (int nt = 0; nt < 4; nt++) {
                int c = wn + nt * 8 + g;
                bf[nt][0] = Bs[kk + t][c];
                bf[nt][1] = Bs[kk + t + 4][c];
            }
#pragma unroll
            for (int mt = 0; mt < 2; mt++)
#pragma unroll
                for (int nt = 0; nt < 4; nt++)
                    mma_tf32(acc[mt][nt], af[mt], bf[nt]);
        }
        __syncthreads();
    }

    // epilogue: d[row, col] layout c0=(g,2t) c1=(g,2t+1) c2=(g+8,2t) c3=(g+8,2t+1)
#pragma unroll
    for (int mt = 0; mt < 2; mt++) {
#pragma unroll
        for (int nt = 0; nt < 4; nt++) {
            int col = n0 + wn + nt * 8 + 2 * t;
            float b0 = bvec[col], b1 = bvec[col + 1];
            int r = m0 + wm + mt * 16 + g;
            float2 o0 = make_float2(alpha * (acc[mt][nt][0] + b0), alpha * (acc[mt][nt][1] + b1));
            float2 o1 = make_float2(alpha * (acc[mt][nt][2] + b0), alpha * (acc[mt][nt][3] + b1));
            *(float2*)&C[(size_t)r * 256 + col] = o0;
            *(float2*)&C[(size_t)(r + 8) * 256 + col] = o1;
        }
    }
}

// Fused QKV variant: blockIdx.z selects projection (0=Q scaled, 1=K, 2=V)
__global__ __launch_bounds__(256) void gemm_tf32_qkv_kernel(
    const float* __restrict__ A,
    const float* __restrict__ Wq, const float* __restrict__ bq,
    const float* __restrict__ Wk, const float* __restrict__ bk,
    const float* __restrict__ Wv, const float* __restrict__ bv)
{
    __shared__ uint32_t As[128][36];
    __shared__ uint32_t Bs[32][72];

    const int z = blockIdx.z;
    const float* W    = (z == 0) ? Wq : (z == 1) ? Wk : Wv;
    const float* bvec = (z == 0) ? bq : (z == 1) ? bk : bv;
    float* C          = (z == 0) ? g_Q : (z == 1) ? g_K : g_V;
    const float alpha = (z == 0) ? 0.17677669529663689f : 1.0f;  // 1/sqrt(32) folded into Q

    const int tid = threadIdx.x;
    const int lane = tid & 31, wid = tid >> 5;
    const int wm = (wid & 3) * 32, wn = (wid >> 2) * 32;
    const int g = lane >> 2, t = lane & 3;
    const int m0 = blockIdx.y * 128, n0 = blockIdx.x * 64;

    float acc[2][4][4] = {};

    for (int k0 = 0; k0 < 256; k0 += 32) {
#pragma unroll
        for (int i = 0; i < 4; i++) {
            int f = tid + i * 256;
            int row = f >> 3, cv = (f & 7) * 4;
            float4 v = *(const float4*)&A[(size_t)(m0 + row) * 256 + k0 + cv];
            uint4 u = make_uint4(f2tf(v.x), f2tf(v.y), f2tf(v.z), f2tf(v.w));
            *(uint4*)&As[row][cv] = u;
        }
#pragma unroll
        for (int i = 0; i < 2; i++) {
            int f = tid + i * 256;
            int row = f >> 4, cv = (f & 15) * 4;
            float4 v = *(const float4*)&W[(size_t)(k0 + row) * 256 + n0 + cv];
            uint4 u = make_uint4(f2tf(v.x), f2tf(v.y), f2tf(v.z), f2tf(v.w));
            *(uint4*)&Bs[row][cv] = u;
        }
        __syncthreads();

#pragma unroll
        for (int kk = 0; kk < 32; kk += 8) {
            uint32_t af[2][4], bf[4][2];
#pragma unroll
            for (int mt = 0; mt < 2; mt++) {
                int r = wm + mt * 16 + g;
                af[mt][0] = As[r][kk + t];
                af[mt][1] = As[r + 8][kk + t];
                af[mt][2] = As[r][kk + t + 4];
                af[mt][3] = As[r + 8][kk + t + 4];
            }
#pragma unroll
            for (int nt = 0; nt < 4; nt++) {
                int c = wn + nt * 8 + g;
                bf[nt][0] = Bs[kk + t][c];
                bf[nt][1] = Bs[kk + t + 4][c];
            }
#pragma unroll
            for (int mt = 0; mt < 2; mt++)
#pragma unroll
                for (int nt = 0; nt < 4; nt++)
                    mma_tf32(acc[mt][nt], af[mt], bf[nt]);
        }
        __syncthreads();
    }

#pragma unroll
    for (int mt = 0; mt < 2; mt++) {
#pragma unroll
        for (int nt = 0; nt < 4; nt++) {
            int col = n0 + wn + nt * 8 + 2 * t;
            float b0 = bvec[col], b1 = bvec[col + 1];
            int r = m0 + wm + mt * 16 + g;
            float2 o0 = make_float2(alpha * (acc[mt][nt][0] + b0), alpha * (acc[mt][nt][1] + b1));
            float2 o1 = make_float2(alpha * (acc[mt][nt][2] + b0), alpha * (acc[mt][nt][3] + b1));
            *(float2*)&C[(size_t)r * 256 + col] = o0;
            *(float2*)&C[(size_t)(r + 8) * 256 + col] = o1;
        }
    }
}

// =====================================================================
// Zero the bias tensor (graph replay must start clean each call)
// =====================================================================
__global__ void zero_bias_kernel()
{
    int i = blockIdx.x * blockDim.x + threadIdx.x;
    ((float4*)g_bias)[i] = make_float4(0.f, 0.f, 0.f, 0.f);
}

// =====================================================================
// Edge bias scatter into [B][q][k][H] layout:
//   total[e,h] = gate_table[type[e]][h] + edge_attr[e,:] @ We[:,h] + be[h]
//   bias[eb, sl, dl, :] += total ; if sl!=dl: bias[eb, dl, sl, :] += total
// 8 contiguous heads -> 2x red.global.add.v4.f32 per direction.
// =====================================================================
__device__ __forceinline__ void red_v4(float* p, float a, float b, float c, float d) {
    asm volatile("red.global.add.v4.f32 [%0], {%1,%2,%3,%4};"
                 :: "l"(p), "f"(a), "f"(b), "f"(c), "f"(d) : "memory");
}

__global__ __launch_bounds__(256) void edge_bias_kernel(
    const float* __restrict__ edge_attr, const int* __restrict__ edge_index,
    const int* __restrict__ gate_type, const float* __restrict__ gate_table,
    const float* __restrict__ We, const float* __restrict__ be)
{
    __shared__ float sGate[160];   // 20 x 8
    __shared__ float sWe[64];      // 8 x 8
    __shared__ float sBe[8];

    const int tid = threadIdx.x;
    if (tid < 160) sGate[tid] = gate_table[tid];
    if (tid < 64)  sWe[tid] = We[tid];
    if (tid < 8)   sBe[tid] = be[tid];
    __syncthreads();

    const int e = blockIdx.x * blockDim.x + tid;
    if (e >= N_EDGE) return;

    const int src = edge_index[e];
    const int dst = edge_index[N_EDGE + e];
    const int eb = src >> 7;          // NPG = 128
    const int sl = src & 127;
    const int dl = dst & 127;
    const int t = gate_type[e];

    float4 ea0 = *(const float4*)&edge_attr[(size_t)e * 8];
    float4 ea1 = *(const float4*)&edge_attr[(size_t)e * 8 + 4];
    float ea[8] = { ea0.x, ea0.y, ea0.z, ea0.w, ea1.x, ea1.y, ea1.z, ea1.w };

    float tot[8];
#pragma unroll
    for (int h = 0; h < 8; h++) {
        float s = sGate[t * 8 + h] + sBe[h];
#pragma unroll
        for (int f = 0; f < 8; f++) s += ea[f] * sWe[f * 8 + h];
        tot[h] = s;
    }

    float* pf = g_bias + ((((size_t)eb * 128 + sl) * 128) + dl) * 8;
    red_v4(pf,     tot[0], tot[1], tot[2], tot[3]);
    red_v4(pf + 4, tot[4], tot[5], tot[6], tot[7]);

    if (sl != dl) {
        float* pr = g_bias + ((((size_t)eb * 128 + dl) * 128) + sl) * 8;
        red_v4(pr,     tot[0], tot[1], tot[2], tot[3]);
        red_v4(pr + 4, tot[4], tot[5], tot[6], tot[7]);
    }
}

// =====================================================================
// Attention: one CTA per (graph b, head h).
// S = (Q Kt) + bias (scale pre-folded into Q) ; P = softmax(S) ; O = P V
// smem: Q/K/V [128][33] + S [128][129]  -> 116,736 B dynamic
// =====================================================================
#define ATTN_SMEM_BYTES ((3 * 128 * 33 + 128 * 129) * 4)

__global__ __launch_bounds__(256, 1) void attn_kernel()
{
    extern __shared__ float sm[];
    float* sQ = sm;
    float* sK = sQ + 128 * 33;
    float* sV = sK + 128 * 33;
    float* sS = sV + 128 * 33;

    const int b = blockIdx.x >> 3;
    const int h = blockIdx.x & 7;
    const int tid = threadIdx.x;

    const float* Qg = g_Q + (size_t)b * NPG * HID + h * HDIM;
    const float* Kg = g_K + (size_t)b * NPG * HID + h * HDIM;
    const float* Vg = g_V + (size_t)b * NPG * HID + h * HDIM;

    for (int idx = tid; idx < NPG * HDIM; idx += 256) {
        int i = idx >> 5, d = idx & 31;
        sQ[i * 33 + d] = Qg[(size_t)i * HID + d];
        sK[i * 33 + d] = Kg[(size_t)i * HID + d];
        sV[i * 33 + d] = Vg[(size_t)i * HID + d];
    }
    __syncthreads();

    // ---- scores: 16x16 threads, each computes an 8x8 block of S ----
    const int tx = tid & 15, ty = tid >> 4;
    const int r0 = ty * 8, c0 = tx * 8;
    {
        float acc[8][8] = {};
#pragma unroll
        for (int d = 0; d < 32; d++) {
            float qa[8], kb[8];
#pragma unroll
            for (int i = 0; i < 8; i++) qa[i] = sQ[(r0 + i) * 33 + d];
#pragma unroll
            for (int j = 0; j < 8; j++) kb[j] = sK[(c0 + j) * 33 + d];
#pragma unroll
            for (int i = 0; i < 8; i++)
#pragma unroll
                for (int j = 0; j < 8; j++) acc[i][j] += qa[i] * kb[j];
        }
#pragma unroll
        for (int i = 0; i < 8; i++)
#pragma unroll
            for (int j = 0; j < 8; j++)
                sS[(r0 + i) * 129 + c0 + j] = acc[i][j];
    }
    __syncthreads();

    // ---- add edge bias: bias[b][q][k][h], stride-8 scalar reads ----
    const float* bg = g_bias + (size_t)b * (NPG * NPG * NHEAD) + h;
    for (int idx = tid; idx < NPG * NPG; idx += 256)
        sS[idx + (idx >> 7)] += bg[(size_t)idx * 8];
    __syncthreads();

    // ---- softmax per row: warp w handles rows 16w..16w+15 ----
    {
        const int w = tid >> 5, lane = tid & 31;
        for (int r = w * 16; r < w * 16 + 16; r++) {
            float* row = sS + r * 129;
            float v0 = row[lane], v1 = row[lane + 32], v2 = row[lane + 64], v3 = row[lane + 96];
            float m = fmaxf(fmaxf(v0, v1), fmaxf(v2, v3));
#pragma unroll
            for (int o = 16; o > 0; o >>= 1) m = fmaxf(m, __shfl_xor_sync(0xffffffffu, m, o));
            float e0 = __expf(v0 - m), e1 = __expf(v1 - m), e2 = __expf(v2 - m), e3 = __expf(v3 - m);
            float s = e0 + e1 + e2 + e3;
#pragma unroll
            for (int o = 16; o > 0; o >>= 1) s += __shfl_xor_sync(0xffffffffu, s, o);
            float inv = 1.0f / s;
            row[lane] = e0 * inv; row[lane + 32] = e1 * inv;
            row[lane + 64] = e2 * inv; row[lane + 96] = e3 * inv;
        }
    }
    __syncthreads();

    // ---- O = P @ V ----
    {
        float o[8][2] = {};
        const int cv = tx * 2;
#pragma unroll 4
        for (int k = 0; k < 128; k++) {
            float v0 = sV[k * 33 + cv];
            float v1 = sV[k * 33 + cv + 1];
#pragma unroll
            for (int i = 0; i < 8; i++) {
                float p = sS[(r0 + i) * 129 + k];
                o[i][0] += p * v0;
                o[i][1] += p * v1;
            }
        }
        float* Og = g_A + (size_t)b * NPG * HID + h * HDIM;
#pragma unroll
        for (int i = 0; i < 8; i++) {
            float2 w2 = make_float2(o[i][0], o[i][1]);
            *(float2*)&Og[(size_t)(r0 + i) * HID + cv] = w2;
        }
    }
}

// =====================================================================
// launch
// =====================================================================
extern "C" void kernel_launch(void* const* d_in, const int* in_sizes, int n_in,
                              void* d_out, int out_size)
{
    const float* x          = (const float*)d_in[0];
    const float* edge_attr  = (const float*)d_in[1];
    const float* Wq         = (const float*)d_in[2];
    const float* bq         = (const float*)d_in[3];
    const float* Wk         = (const float*)d_in[4];
    const float* bk         = (const float*)d_in[5];
    const float* Wv         = (const float*)d_in[6];
    const float* bv         = (const float*)d_in[7];
    const float* Wo         = (const float*)d_in[8];
    const float* bo         = (const float*)d_in[9];
    const float* gate_table = (const float*)d_in[10];
    const float* We         = (const float*)d_in[11];
    const float* be         = (const float*)d_in[12];
    const int*   edge_index = (const int*)d_in[13];
    const int*   gate_type  = (const int*)d_in[14];
    float*       out        = (float*)d_out;

    float* Ap;
    cudaGetSymbolAddress((void**)&Ap, g_A);

    cudaFuncSetAttribute(attn_kernel, cudaFuncAttributeMaxDynamicSharedMemorySize,
                         ATTN_SMEM_BYTES);

    // bias zero + scatter first, then QKV (bias not needed until attn)
    zero_bias_kernel<<<BIAS_ELEMS / 4 / 256, 256>>>();
    edge_bias_kernel<<<N_EDGE / 256, 256>>>(edge_attr, edge_index, gate_type,
                                            gate_table, We, be);

    dim3 gqkv(HID / 64, N_NODES / 128, 3);   // (4, 256, 3)
    gemm_tf32_qkv_kernel<<<gqkv, 256>>>(x, Wq, bq, Wk, bk, Wv, bv);

    attn_kernel<<<N_GRAPH * NHEAD, 256, ATTN_SMEM_BYTES>>>();

    dim3 go(HID / 64, N_NODES / 128);        // (4, 256)
    gemm_tf32_kernel<<<go, 256>>>(Ap, Wo, bo, out, 1.0f);
}

// round 9
// speedup vs baseline: 2.5281x; 1.5665x over previous
#include <cuda_runtime.h>
#include <cuda_bf16.h>
#include <cstdint>

// ---------------- problem constants ----------------
#define N_NODES 32768
#define HID     256
#define N_GRAPH 256
#define NPG     128
#define NHEAD   8
#define HDIM    32
#define N_EDGE  524288
#define BIAS_ELEMS (N_GRAPH * NHEAD * NPG * NPG)   // 33,554,432 floats, layout [B][H][q][k]

// ---------------- scratch (no allocs allowed) ----------------
__device__ float g_Q[N_NODES * HID];
__device__ float g_K[N_NODES * HID];
__device__ float g_V[N_NODES * HID];
__device__ float g_A[N_NODES * HID];           // attention output before Wo
__device__ float g_bias[BIAS_ELEMS];

// =====================================================================
// tf32 helpers
// =====================================================================
__device__ __forceinline__ uint32_t f2tf(float x) {
    uint32_t r;
    asm("cvt.rna.tf32.f32 %0, %1;" : "=r"(r) : "f"(x));
    return r;
}

__device__ __forceinline__ void mma_tf32(float acc[4], const uint32_t a[4], const uint32_t b[2]) {
    asm volatile(
        "mma.sync.aligned.m16n8k8.row.col.f32.tf32.tf32.f32 "
        "{%0,%1,%2,%3}, {%4,%5,%6,%7}, {%8,%9}, {%0,%1,%2,%3};\n"
        : "+f"(acc[0]), "+f"(acc[1]), "+f"(acc[2]), "+f"(acc[3])
        : "r"(a[0]), "r"(a[1]), "r"(a[2]), "r"(a[3]), "r"(b[0]), "r"(b[1]));
}

// =====================================================================
// tf32 tensor-core GEMM: C[M,256] = alpha * (A[M,256] @ W[256,256] + bvec)
// CTA tile 128x64, BK=32, 8 warps (warp tile 32x32), m16n8k8 mma.
// =====================================================================
__global__ __launch_bounds__(256) void gemm_tf32_kernel(
    const float* __restrict__ A, const float* __restrict__ W,
    const float* __restrict__ bvec, float* __restrict__ C, float alpha)
{
    __shared__ uint32_t As[128][36];
    __shared__ uint32_t Bs[32][72];

    const int tid = threadIdx.x;
    const int lane = tid & 31, wid = tid >> 5;
    const int wm = (wid & 3) * 32, wn = (wid >> 2) * 32;
    const int g = lane >> 2, t = lane & 3;
    const int m0 = blockIdx.y * 128, n0 = blockIdx.x * 64;

    float acc[2][4][4] = {};

    for (int k0 = 0; k0 < 256; k0 += 32) {
#pragma unroll
        for (int i = 0; i < 4; i++) {
            int f = tid + i * 256;
            int row = f >> 3, cv = (f & 7) * 4;
            float4 v = *(const float4*)&A[(size_t)(m0 + row) * 256 + k0 + cv];
            uint4 u = make_uint4(f2tf(v.x), f2tf(v.y), f2tf(v.z), f2tf(v.w));
            *(uint4*)&As[row][cv] = u;
        }
#pragma unroll
        for (int i = 0; i < 2; i++) {
            int f = tid + i * 256;
            int row = f >> 4, cv = (f & 15) * 4;
            float4 v = *(const float4*)&W[(size_t)(k0 + row) * 256 + n0 + cv];
            uint4 u = make_uint4(f2tf(v.x), f2tf(v.y), f2tf(v.z), f2tf(v.w));
            *(uint4*)&Bs[row][cv] = u;
        }
        __syncthreads();

#pragma unroll
        for (int kk = 0; kk < 32; kk += 8) {
            uint32_t af[2][4], bf[4][2];
#pragma unroll
            for (int mt = 0; mt < 2; mt++) {
                int r = wm + mt * 16 + g;
                af[mt][0] = As[r][kk + t];
                af[mt][1] = As[r + 8][kk + t];
                af[mt][2] = As[r][kk + t + 4];
                af[mt][3] = As[r + 8][kk + t + 4];
            }
#pragma unroll
            for (int nt = 0; nt < 4; nt++) {
                int c = wn + nt * 8 + g;
                bf[nt][0] = Bs[kk + t][c];
                bf[nt][1] = Bs[kk + t + 4][c];
            }
#pragma unroll
            for (int mt = 0; mt < 2; mt++)
#pragma unroll
                for (int nt = 0; nt < 4; nt++)
                    mma_tf32(acc[mt][nt], af[mt], bf[nt]);
        }
        __syncthreads();
    }

#pragma unroll
    for (int mt = 0; mt < 2; mt++) {
#pragma unroll
        for (int nt = 0; nt < 4; nt++) {
            int col = n0 + wn + nt * 8 + 2 * t;
            float b0 = bvec[col], b1 = bvec[col + 1];
            int r = m0 + wm + mt * 16 + g;
            float2 o0 = make_float2(alpha * (acc[mt][nt][0] + b0), alpha * (acc[mt][nt][1] + b1));
            float2 o1 = make_float2(alpha * (acc[mt][nt][2] + b0), alpha * (acc[mt][nt][3] + b1));
            *(float2*)&C[(size_t)r * 256 + col] = o0;
            *(float2*)&C[(size_t)(r + 8) * 256 + col] = o1;
        }
    }
}

// Fused QKV variant: blockIdx.z selects projection (0=Q scaled, 1=K, 2=V)
__global__ __launch_bounds__(256) void gemm_tf32_qkv_kernel(
    const float* __restrict__ A,
    const float* __restrict__ Wq, const float* __restrict__ bq,
    const float* __restrict__ Wk, const float* __restrict__ bk,
    const float* __restrict__ Wv, const float* __restrict__ bv)
{
    __shared__ uint32_t As[128][36];
    __shared__ uint32_t Bs[32][72];

    const int z = blockIdx.z;
    const float* W    = (z == 0) ? Wq : (z == 1) ? Wk : Wv;
    const float* bvec = (z == 0) ? bq : (z == 1) ? bk : bv;
    float* C          = (z == 0) ? g_Q : (z == 1) ? g_K : g_V;
    const float alpha = (z == 0) ? 0.17677669529663689f : 1.0f;  // 1/sqrt(32) folded into Q

    const int tid = threadIdx.x;
    const int lane = tid & 31, wid = tid >> 5;
    const int wm = (wid & 3) * 32, wn = (wid >> 2) * 32;
    const int g = lane >> 2, t = lane & 3;
    const int m0 = blockIdx.y * 128, n0 = blockIdx.x * 64;

    float acc[2][4][4] = {};

    for (int k0 = 0; k0 < 256; k0 += 32) {
#pragma unroll
        for (int i = 0; i < 4; i++) {
            int f = tid + i * 256;
            int row = f >> 3, cv = (f & 7) * 4;
            float4 v = *(const float4*)&A[(size_t)(m0 + row) * 256 + k0 + cv];
            uint4 u = make_uint4(f2tf(v.x), f2tf(v.y), f2tf(v.z), f2tf(v.w));
            *(uint4*)&As[row][cv] = u;
        }
#pragma unroll
        for (int i = 0; i < 2; i++) {
            int f = tid + i * 256;
            int row = f >> 4, cv = (f & 15) * 4;
            float4 v = *(const float4*)&W[(size_t)(k0 + row) * 256 + n0 + cv];
            uint4 u = make_uint4(f2tf(v.x), f2tf(v.y), f2tf(v.z), f2tf(v.w));
            *(uint4*)&Bs[row][cv] = u;
        }
        __syncthreads();

#pragma unroll
        for (int kk = 0; kk < 32; kk += 8) {
            uint32_t af[2][4], bf[4][2];
#pragma unroll
            for (int mt = 0; mt < 2; mt++) {
                int r = wm + mt * 16 + g;
                af[mt][0] = As[r][kk + t];
                af[mt][1] = As[r + 8][kk + t];
                af[mt][2] = As[r][kk + t + 4];
                af[mt][3] = As[r + 8][kk + t + 4];
            }
#pragma unroll
            for (int nt = 0; nt < 4; nt++) {
                int c = wn + nt * 8 + g;
                bf[nt][0] = Bs[kk + t][c];
                bf[nt][1] = Bs[kk + t + 4][c];
            }
#pragma unroll
            for (int mt = 0; mt < 2; mt++)
#pragma unroll
                for (int nt = 0; nt < 4; nt++)
                    mma_tf32(acc[mt][nt], af[mt], bf[nt]);
        }
        __syncthreads();
    }

#pragma unroll
    for (int mt = 0; mt < 2; mt++) {
#pragma unroll
        for (int nt = 0; nt < 4; nt++) {
            int col = n0 + wn + nt * 8 + 2 * t;
            float b0 = bvec[col], b1 = bvec[col + 1];
            int r = m0 + wm + mt * 16 + g;
            float2 o0 = make_float2(alpha * (acc[mt][nt][0] + b0), alpha * (acc[mt][nt][1] + b1));
            float2 o1 = make_float2(alpha * (acc[mt][nt][2] + b0), alpha * (acc[mt][nt][3] + b1));
            *(float2*)&C[(size_t)r * 256 + col] = o0;
            *(float2*)&C[(size_t)(r + 8) * 256 + col] = o1;
        }
    }
}

// =====================================================================
// Zero the bias tensor (graph replay must start clean each call)
// =====================================================================
__global__ void zero_bias_kernel()
{
    int i = blockIdx.x * blockDim.x + threadIdx.x;
    ((float4*)g_bias)[i] = make_float4(0.f, 0.f, 0.f, 0.f);
}

// =====================================================================
// Edge bias scatter into HEAD-MAJOR layout [B][H][q][k]:
//   total[e,h] = gate_table[type[e]][h] + edge_attr[e,:] @ We[:,h] + be[h]
//   bias[eb, h, sl, dl] += total ; if sl!=dl: bias[eb, h, dl, sl] += total
// =====================================================================
__device__ __forceinline__ void red_f32(float* p, float v) {
    asm volatile("red.global.add.f32 [%0], %1;" :: "l"(p), "f"(v) : "memory");
}

__global__ __launch_bounds__(256) void edge_bias_kernel(
    const float* __restrict__ edge_attr, const int* __restrict__ edge_index,
    const int* __restrict__ gate_type, const float* __restrict__ gate_table,
    const float* __restrict__ We, const float* __restrict__ be)
{
    __shared__ float sGate[160];   // 20 x 8
    __shared__ float sWe[64];      // 8 x 8
    __shared__ float sBe[8];

    const int tid = threadIdx.x;
    if (tid < 160) sGate[tid] = gate_table[tid];
    if (tid < 64)  sWe[tid] = We[tid];
    if (tid < 8)   sBe[tid] = be[tid];
    __syncthreads();

    const int e = blockIdx.x * blockDim.x + tid;
    if (e >= N_EDGE) return;

    const int src = edge_index[e];
    const int dst = edge_index[N_EDGE + e];
    const int eb = src >> 7;          // NPG = 128
    const int sl = src & 127;
    const int dl = dst & 127;
    const int t = gate_type[e];

    float4 ea0 = *(const float4*)&edge_attr[(size_t)e * 8];
    float4 ea1 = *(const float4*)&edge_attr[(size_t)e * 8 + 4];
    float ea[8] = { ea0.x, ea0.y, ea0.z, ea0.w, ea1.x, ea1.y, ea1.z, ea1.w };

    float tot[8];
#pragma unroll
    for (int h = 0; h < 8; h++) {
        float s = sGate[t * 8 + h] + sBe[h];
#pragma unroll
        for (int f = 0; f < 8; f++) s += ea[f] * sWe[f * 8 + h];
        tot[h] = s;
    }

    float* baseF = g_bias + (size_t)eb * (8 * 16384) + sl * 128 + dl;
#pragma unroll
    for (int h = 0; h < 8; h++)
        red_f32(baseF + h * 16384, tot[h]);

    if (sl != dl) {
        float* baseR = g_bias + (size_t)eb * (8 * 16384) + dl * 128 + sl;
#pragma unroll
        for (int h = 0; h < 8; h++)
            red_f32(baseR + h * 16384, tot[h]);
    }
}

// =====================================================================
// Tensor-core attention. CTA = (graph b, head h, q-half). 4 warps.
// Warp w owns 16 q-rows. S fragments in registers; bias add + softmax
// on fragments; P -> smem (tf32); PV via mma with V B-frags from gmem.
// smem: Q[64][36] + K[128][36] + P[64][132] tf32 = 61440 B -> 3 CTAs/SM
// =====================================================================
#define ATTN_SMEM_BYTES ((64 * 36 + 128 * 36 + 64 * 132) * 4)

__global__ __launch_bounds__(128, 3) void attn_mma_kernel()
{
    extern __shared__ uint32_t smx[];
    uint32_t* sQ = smx;                 // [64][36]
    uint32_t* sK = smx + 64 * 36;       // [128][36]
    uint32_t* sP = smx + 64 * 36 + 128 * 36;  // [64][132]

    const int bid = blockIdx.x;
    const int b  = bid >> 4;
    const int h  = (bid >> 1) & 7;
    const int q0 = (bid & 1) * 64;

    const int tid = threadIdx.x;
    const int lane = tid & 31, w = tid >> 5;
    const int g = lane >> 2, t = lane & 3;

    const float* Qg = g_Q + ((size_t)(b * NPG + q0)) * HID + h * HDIM;
    const float* Kg = g_K + ((size_t)b * NPG) * HID + h * HDIM;
    const float* Vg = g_V + ((size_t)b * NPG) * HID + h * HDIM;

    // ---- load Q (64x32) and K (128x32) as tf32 into smem ----
#pragma unroll
    for (int i = 0; i < 4; i++) {
        int f = tid + i * 128;
        int row = f >> 3, cv = (f & 7) * 4;
        float4 v = *(const float4*)&Qg[(size_t)row * HID + cv];
        uint4 u = make_uint4(f2tf(v.x), f2tf(v.y), f2tf(v.z), f2tf(v.w));
        *(uint4*)&sQ[row * 36 + cv] = u;
    }
#pragma unroll
    for (int i = 0; i < 8; i++) {
        int f = tid + i * 128;
        int row = f >> 3, cv = (f & 7) * 4;
        float4 v = *(const float4*)&Kg[(size_t)row * HID + cv];
        uint4 u = make_uint4(f2tf(v.x), f2tf(v.y), f2tf(v.z), f2tf(v.w));
        *(uint4*)&sK[row * 36 + cv] = u;
    }
    __syncthreads();

    const int r = w * 16 + g;   // this thread's base q-row (CTA-local)

    // ---- QK^T : S strip 16x128 per warp, in fragments ----
    uint32_t af[4][4];
#pragma unroll
    for (int ks = 0; ks < 4; ks++) {
        af[ks][0] = sQ[r * 36 + ks * 8 + t];
        af[ks][1] = sQ[(r + 8) * 36 + ks * 8 + t];
        af[ks][2] = sQ[r * 36 + ks * 8 + t + 4];
        af[ks][3] = sQ[(r + 8) * 36 + ks * 8 + t + 4];
    }

    float acc[16][4];
#pragma unroll
    for (int j = 0; j < 16; j++)
        acc[j][0] = acc[j][1] = acc[j][2] = acc[j][3] = 0.f;

#pragma unroll
    for (int j = 0; j < 16; j++) {
        int c = j * 8 + g;
#pragma unroll
        for (int ks = 0; ks < 4; ks++) {
            uint32_t bf[2];
            bf[0] = sK[c * 36 + ks * 8 + t];
            bf[1] = sK[c * 36 + ks * 8 + t + 4];
            mma_tf32(acc[j], af[ks], bf);
        }
    }

    // ---- add bias (head-major, coalesced float2 reads) ----
    const float* bg = g_bias + ((size_t)(b * NHEAD + h) * NPG + q0 + w * 16) * NPG;
#pragma unroll
    for (int j = 0; j < 16; j++) {
        float2 b0 = *(const float2*)&bg[g * NPG + j * 8 + 2 * t];
        float2 b1 = *(const float2*)&bg[(g + 8) * NPG + j * 8 + 2 * t];
        acc[j][0] += b0.x; acc[j][1] += b0.y;
        acc[j][2] += b1.x; acc[j][3] += b1.y;
    }

    // ---- softmax on fragments (rows g and g+8; 4 lanes per row) ----
    float m1 = -1e30f, m2 = -1e30f;
#pragma unroll
    for (int j = 0; j < 16; j++) {
        m1 = fmaxf(m1, fmaxf(acc[j][0], acc[j][1]));
        m2 = fmaxf(m2, fmaxf(acc[j][2], acc[j][3]));
    }
    m1 = fmaxf(m1, __shfl_xor_sync(0xffffffffu, m1, 1));
    m1 = fmaxf(m1, __shfl_xor_sync(0xffffffffu, m1, 2));
    m2 = fmaxf(m2, __shfl_xor_sync(0xffffffffu, m2, 1));
    m2 = fmaxf(m2, __shfl_xor_sync(0xffffffffu, m2, 2));

    float s1 = 0.f, s2 = 0.f;
#pragma unroll
    for (int j = 0; j < 16; j++) {
        acc[j][0] = __expf(acc[j][0] - m1);
        acc[j][1] = __expf(acc[j][1] - m1);
        acc[j][2] = __expf(acc[j][2] - m2);
        acc[j][3] = __expf(acc[j][3] - m2);
        s1 += acc[j][0] + acc[j][1];
        s2 += acc[j][2] + acc[j][3];
    }
    s1 += __shfl_xor_sync(0xffffffffu, s1, 1);
    s1 += __shfl_xor_sync(0xffffffffu, s1, 2);
    s2 += __shfl_xor_sync(0xffffffffu, s2, 1);
    s2 += __shfl_xor_sync(0xffffffffu, s2, 2);
    const float inv1 = 1.0f / s1, inv2 = 1.0f / s2;

    // ---- P -> smem (tf32) ----
#pragma unroll
    for (int j = 0; j < 16; j++) {
        uint2 p0 = make_uint2(f2tf(acc[j][0] * inv1), f2tf(acc[j][1] * inv1));
        uint2 p1 = make_uint2(f2tf(acc[j][2] * inv2), f2tf(acc[j][3] * inv2));
        *(uint2*)&sP[r * 132 + j * 8 + 2 * t] = p0;
        *(uint2*)&sP[(r + 8) * 132 + j * 8 + 2 * t] = p1;
    }
    __syncwarp();   // warp-private strip; just order STS before LDS across lanes

    // ---- O = P @ V via mma (V B-frags from gmem, L1-resident) ----
    float o[4][4] = {};
#pragma unroll
    for (int ks = 0; ks < 16; ks++) {
        uint32_t pf[4];
        pf[0] = sP[r * 132 + ks * 8 + t];
        pf[1] = sP[(r + 8) * 132 + ks * 8 + t];
        pf[2] = sP[r * 132 + ks * 8 + t + 4];
        pf[3] = sP[(r + 8) * 132 + ks * 8 + t + 4];
#pragma unroll
        for (int nt = 0; nt < 4; nt++) {
            uint32_t bf[2];
            bf[0] = f2tf(Vg[(size_t)(ks * 8 + t) * HID + nt * 8 + g]);
            bf[1] = f2tf(Vg[(size_t)(ks * 8 + t + 4) * HID + nt * 8 + g]);
            mma_tf32(o[nt], pf, bf);
        }
    }

    // ---- store O ----
    float* Og = g_A + ((size_t)(b * NPG + q0 + w * 16)) * HID + h * HDIM;
#pragma unroll
    for (int nt = 0; nt < 4; nt++) {
        int col = nt * 8 + 2 * t;
        *(float2*)&Og[(size_t)g * HID + col] = make_float2(o[nt][0], o[nt][1]);
        *(float2*)&Og[(size_t)(g + 8) * HID + col] = make_float2(o[nt][2], o[nt][3]);
    }
}

// =====================================================================
// launch
// =====================================================================
extern "C" void kernel_launch(void* const* d_in, const int* in_sizes, int n_in,
                              void* d_out, int out_size)
{
    const float* x          = (const float*)d_in[0];
    const float* edge_attr  = (const float*)d_in[1];
    const float* Wq         = (const float*)d_in[2];
    const float* bq         = (const float*)d_in[3];
    const float* Wk         = (const float*)d_in[4];
    const float* bk         = (const float*)d_in[5];
    const float* Wv         = (const float*)d_in[6];
    const float* bv         = (const float*)d_in[7];
    const float* Wo         = (const float*)d_in[8];
    const float* bo         = (const float*)d_in[9];
    const float* gate_table = (const float*)d_in[10];
    const float* We         = (const float*)d_in[11];
    const float* be         = (const float*)d_in[12];
    const int*   edge_index = (const int*)d_in[13];
    const int*   gate_type  = (const int*)d_in[14];
    float*       out        = (float*)d_out;

    float* Ap;
    cudaGetSymbolAddress((void**)&Ap, g_A);

    cudaFuncSetAttribute(attn_mma_kernel, cudaFuncAttributeMaxDynamicSharedMemorySize,
                         ATTN_SMEM_BYTES);

    // bias zero + scatter first, then QKV (bias not needed until attn)
    zero_bias_kernel<<<BIAS_ELEMS / 4 / 256, 256>>>();
    edge_bias_kernel<<<N_EDGE / 256, 256>>>(edge_attr, edge_index, gate_type,
                                            gate_table, We, be);

    dim3 gqkv(HID / 64, N_NODES / 128, 3);   // (4, 256, 3)
    gemm_tf32_qkv_kernel<<<gqkv, 256>>>(x, Wq, bq, Wk, bk, Wv, bv);

    attn_mma_kernel<<<N_GRAPH * NHEAD * 2, 128, ATTN_SMEM_BYTES>>>();

    dim3 go(HID / 64, N_NODES / 128);        // (4, 256)
    gemm_tf32_kernel<<<go, 256>>>(Ap, Wo, bo, out, 1.0f);
}

// round 10
// speedup vs baseline: 3.0844x; 1.2200x over previous
#include <cuda_runtime.h>
#include <cuda_bf16.h>
#include <cstdint>

// ---------------- problem constants ----------------
#define N_NODES 32768
#define HID     256
#define N_GRAPH 256
#define NPG     128
#define NHEAD   8
#define HDIM    32
#define N_EDGE  524288
#define BIAS_ELEMS (N_GRAPH * NHEAD * NPG * NPG)   // 33,554,432 floats

// ---------------- scratch (no allocs allowed) ----------------
__device__ float g_Q[N_NODES * HID];
__device__ float g_K[N_NODES * HID];
__device__ float g_V[N_NODES * HID];
__device__ float g_A[N_NODES * HID];            // attention output before Wo
__device__ float g_biasS[BIAS_ELEMS];           // scatter layout [B][q][k][H]
__device__ float g_bias[BIAS_ELEMS];            // head-major  [B][H][q][k]

// =====================================================================
// tf32 helpers
// =====================================================================
__device__ __forceinline__ uint32_t f2tf(float x) {
    uint32_t r;
    asm("cvt.rna.tf32.f32 %0, %1;" : "=r"(r) : "f"(x));
    return r;
}

__device__ __forceinline__ void mma_tf32(float acc[4], const uint32_t a[4], const uint32_t b[2]) {
    asm volatile(
        "mma.sync.aligned.m16n8k8.row.col.f32.tf32.tf32.f32 "
        "{%0,%1,%2,%3}, {%4,%5,%6,%7}, {%8,%9}, {%0,%1,%2,%3};\n"
        : "+f"(acc[0]), "+f"(acc[1]), "+f"(acc[2]), "+f"(acc[3])
        : "r"(a[0]), "r"(a[1]), "r"(a[2]), "r"(a[3]), "r"(b[0]), "r"(b[1]));
}

// =====================================================================
// tf32 tensor-core GEMM: C[M,256] = alpha * (A[M,256] @ W[256,256] + bvec)
// CTA tile 128x64, BK=32, 8 warps (warp tile 32x32), m16n8k8 mma.
// =====================================================================
__global__ __launch_bounds__(256) void gemm_tf32_kernel(
    const float* __restrict__ A, const float* __restrict__ W,
    const float* __restrict__ bvec, float* __restrict__ C, float alpha)
{
    __shared__ uint32_t As[128][36];
    __shared__ uint32_t Bs[32][72];

    const int tid = threadIdx.x;
    const int lane = tid & 31, wid = tid >> 5;
    const int wm = (wid & 3) * 32, wn = (wid >> 2) * 32;
    const int g = lane >> 2, t = lane & 3;
    const int m0 = blockIdx.y * 128, n0 = blockIdx.x * 64;

    float acc[2][4][4] = {};

    for (int k0 = 0; k0 < 256; k0 += 32) {
#pragma unroll
        for (int i = 0; i < 4; i++) {
            int f = tid + i * 256;
            int row = f >> 3, cv = (f & 7) * 4;
            float4 v = *(const float4*)&A[(size_t)(m0 + row) * 256 + k0 + cv];
            uint4 u = make_uint4(f2tf(v.x), f2tf(v.y), f2tf(v.z), f2tf(v.w));
            *(uint4*)&As[row][cv] = u;
        }
#pragma unroll
        for (int i = 0; i < 2; i++) {
            int f = tid + i * 256;
            int row = f >> 4, cv = (f & 15) * 4;
            float4 v = *(const float4*)&W[(size_t)(k0 + row) * 256 + n0 + cv];
            uint4 u = make_uint4(f2tf(v.x), f2tf(v.y), f2tf(v.z), f2tf(v.w));
            *(uint4*)&Bs[row][cv] = u;
        }
        __syncthreads();

#pragma unroll
        for (int kk = 0; kk < 32; kk += 8) {
            uint32_t af[2][4], bf[4][2];
#pragma unroll
            for (int mt = 0; mt < 2; mt++) {
                int r = wm + mt * 16 + g;
                af[mt][0] = As[r][kk + t];
                af[mt][1] = As[r + 8][kk + t];
                af[mt][2] = As[r][kk + t + 4];
                af[mt][3] = As[r + 8][kk + t + 4];
            }
#pragma unroll
            for (int nt = 0; nt < 4; nt++) {
                int c = wn + nt * 8 + g;
                bf[nt][0] = Bs[kk + t][c];
                bf[nt][1] = Bs[kk + t + 4][c];
            }
#pragma unroll
            for (int mt = 0; mt < 2; mt++)
#pragma unroll
                for (int nt = 0; nt < 4; nt++)
                    mma_tf32(acc[mt][nt], af[mt], bf[nt]);
        }
        __syncthreads();
    }

#pragma unroll
    for (int mt = 0; mt < 2; mt++) {
#pragma unroll
        for (int nt = 0; nt < 4; nt++) {
            int col = n0 + wn + nt * 8 + 2 * t;
            float b0 = bvec[col], b1 = bvec[col + 1];
            int r = m0 + wm + mt * 16 + g;
            float2 o0 = make_float2(alpha * (acc[mt][nt][0] + b0), alpha * (acc[mt][nt][1] + b1));
            float2 o1 = make_float2(alpha * (acc[mt][nt][2] + b0), alpha * (acc[mt][nt][3] + b1));
            *(float2*)&C[(size_t)r * 256 + col] = o0;
            *(float2*)&C[(size_t)(r + 8) * 256 + col] = o1;
        }
    }
}

// Fused QKV variant: blockIdx.z selects projection (0=Q scaled, 1=K, 2=V)
__global__ __launch_bounds__(256) void gemm_tf32_qkv_kernel(
    const float* __restrict__ A,
    const float* __restrict__ Wq, const float* __restrict__ bq,
    const float* __restrict__ Wk, const float* __restrict__ bk,
    const float* __restrict__ Wv, const float* __restrict__ bv)
{
    __shared__ uint32_t As[128][36];
    __shared__ uint32_t Bs[32][72];

    const int z = blockIdx.z;
    const float* W    = (z == 0) ? Wq : (z == 1) ? Wk : Wv;
    const float* bvec = (z == 0) ? bq : (z == 1) ? bk : bv;
    float* C          = (z == 0) ? g_Q : (z == 1) ? g_K : g_V;
    const float alpha = (z == 0) ? 0.17677669529663689f : 1.0f;  // 1/sqrt(32) folded into Q

    const int tid = threadIdx.x;
    const int lane = tid & 31, wid = tid >> 5;
    const int wm = (wid & 3) * 32, wn = (wid >> 2) * 32;
    const int g = lane >> 2, t = lane & 3;
    const int m0 = blockIdx.y * 128, n0 = blockIdx.x * 64;

    float acc[2][4][4] = {};

    for (int k0 = 0; k0 < 256; k0 += 32) {
#pragma unroll
        for (int i = 0; i < 4; i++) {
            int f = tid + i * 256;
            int row = f >> 3, cv = (f & 7) * 4;
            float4 v = *(const float4*)&A[(size_t)(m0 + row) * 256 + k0 + cv];
            uint4 u = make_uint4(f2tf(v.x), f2tf(v.y), f2tf(v.z), f2tf(v.w));
            *(uint4*)&As[row][cv] = u;
        }
#pragma unroll
        for (int i = 0; i < 2; i++) {
            int f = tid + i * 256;
            int row = f >> 4, cv = (f & 15) * 4;
            float4 v = *(const float4*)&W[(size_t)(k0 + row) * 256 + n0 + cv];
            uint4 u = make_uint4(f2tf(v.x), f2tf(v.y), f2tf(v.z), f2tf(v.w));
            *(uint4*)&Bs[row][cv] = u;
        }
        __syncthreads();

#pragma unroll
        for (int kk = 0; kk < 32; kk += 8) {
            uint32_t af[2][4], bf[4][2];
#pragma unroll
            for (int mt = 0; mt < 2; mt++) {
                int r = wm + mt * 16 + g;
                af[mt][0] = As[r][kk + t];
                af[mt][1] = As[r + 8][kk + t];
                af[mt][2] = As[r][kk + t + 4];
                af[mt][3] = As[r + 8][kk + t + 4];
            }
#pragma unroll
            for (int nt = 0; nt < 4; nt++) {
                int c = wn + nt * 8 + g;
                bf[nt][0] = Bs[kk + t][c];
                bf[nt][1] = Bs[kk + t + 4][c];
            }
#pragma unroll
            for (int mt = 0; mt < 2; mt++)
#pragma unroll
                for (int nt = 0; nt < 4; nt++)
                    mma_tf32(acc[mt][nt], af[mt], bf[nt]);
        }
        __syncthreads();
    }

#pragma unroll
    for (int mt = 0; mt < 2; mt++) {
#pragma unroll
        for (int nt = 0; nt < 4; nt++) {
            int col = n0 + wn + nt * 8 + 2 * t;
            float b0 = bvec[col], b1 = bvec[col + 1];
            int r = m0 + wm + mt * 16 + g;
            float2 o0 = make_float2(alpha * (acc[mt][nt][0] + b0), alpha * (acc[mt][nt][1] + b1));
            float2 o1 = make_float2(alpha * (acc[mt][nt][2] + b0), alpha * (acc[mt][nt][3] + b1));
            *(float2*)&C[(size_t)r * 256 + col] = o0;
            *(float2*)&C[(size_t)(r + 8) * 256 + col] = o1;
        }
    }
}

// =====================================================================
// Zero the scatter buffer (graph replay must start clean each call)
// =====================================================================
__global__ void zero_bias_kernel()
{
    int i = blockIdx.x * blockDim.x + threadIdx.x;
    ((float4*)g_biasS)[i] = make_float4(0.f, 0.f, 0.f, 0.f);
}

// =====================================================================
// Edge bias scatter into [B][q][k][H] staging layout (vectorized atomics):
//   total[e,h] = gate_table[type[e]][h] + edge_attr[e,:] @ We[:,h] + be[h]
//   biasS[eb, sl, dl, :] += total ; if sl!=dl: biasS[eb, dl, sl, :] += total
// =====================================================================
__device__ __forceinline__ void red_v4(float* p, float a, float b, float c, float d) {
    asm volatile("red.global.add.v4.f32 [%0], {%1,%2,%3,%4};"
                 :: "l"(p), "f"(a), "f"(b), "f"(c), "f"(d) : "memory");
}

__global__ __launch_bounds__(256) void edge_bias_kernel(
    const float* __restrict__ edge_attr, const int* __restrict__ edge_index,
    const int* __restrict__ gate_type, const float* __restrict__ gate_table,
    const float* __restrict__ We, const float* __restrict__ be)
{
    __shared__ float sGate[160];   // 20 x 8
    __shared__ float sWe[64];      // 8 x 8
    __shared__ float sBe[8];

    const int tid = threadIdx.x;
    if (tid < 160) sGate[tid] = gate_table[tid];
    if (tid < 64)  sWe[tid] = We[tid];
    if (tid < 8)   sBe[tid] = be[tid];
    __syncthreads();

    const int e = blockIdx.x * blockDim.x + tid;
    if (e >= N_EDGE) return;

    const int src = edge_index[e];
    const int dst = edge_index[N_EDGE + e];
    const int eb = src >> 7;          // NPG = 128
    const int sl = src & 127;
    const int dl = dst & 127;
    const int t = gate_type[e];

    float4 ea0 = *(const float4*)&edge_attr[(size_t)e * 8];
    float4 ea1 = *(const float4*)&edge_attr[(size_t)e * 8 + 4];
    float ea[8] = { ea0.x, ea0.y, ea0.z, ea0.w, ea1.x, ea1.y, ea1.z, ea1.w };

    float tot[8];
#pragma unroll
    for (int h = 0; h < 8; h++) {
        float s = sGate[t * 8 + h] + sBe[h];
#pragma unroll
        for (int f = 0; f < 8; f++) s += ea[f] * sWe[f * 8 + h];
        tot[h] = s;
    }

    float* pf = g_biasS + ((((size_t)eb * 128 + sl) * 128) + dl) * 8;
    red_v4(pf,     tot[0], tot[1], tot[2], tot[3]);
    red_v4(pf + 4, tot[4], tot[5], tot[6], tot[7]);

    if (sl != dl) {
        float* pr = g_biasS + ((((size_t)eb * 128 + dl) * 128) + sl) * 8;
        red_v4(pr,     tot[0], tot[1], tot[2], tot[3]);
        red_v4(pr + 4, tot[4], tot[5], tot[6], tot[7]);
    }
}

// =====================================================================
// Transpose bias: [B][q][k][H] -> [B][H][q][k]
// CTA handles 2 global (b,q) rows. Reads and writes fully coalesced.
// =====================================================================
__global__ __launch_bounds__(256) void transpose_bias_kernel()
{
    __shared__ float s[2][128][9];   // [row][k][h] padded
    const int t = threadIdx.x;
    const int r = t >> 7, j = t & 127;
    const int gq = blockIdx.x * 2 + r;

    const float4* in = (const float4*)(g_biasS + (size_t)gq * 1024);
#pragma unroll
    for (int i = 0; i < 2; i++) {
        int v = j + i * 128;               // float4 index 0..255
        float4 a = in[v];
        int k = v >> 1, h4 = (v & 1) * 4;
        s[r][k][h4 + 0] = a.x; s[r][k][h4 + 1] = a.y;
        s[r][k][h4 + 2] = a.z; s[r][k][h4 + 3] = a.w;
    }
    __syncthreads();

    const int b = gq >> 7, q = gq & 127;
    const int h = j >> 4, kc0 = j & 15;
    float4* outp = (float4*)(g_bias + (((size_t)(b * 8 + h) * 128 + q) * 128));
#pragma unroll
    for (int i = 0; i < 2; i++) {
        int kc = kc0 + i * 16;
        float4 o = make_float4(s[r][kc * 4 + 0][h], s[r][kc * 4 + 1][h],
                               s[r][kc * 4 + 2][h], s[r][kc * 4 + 3][h]);
        outp[kc] = o;
    }
}

// =====================================================================
// Tensor-core attention. CTA = (graph b, head h, q-half). 4 warps.
// S fragments in registers; bias add + softmax on fragments;
// P -> smem (tf32); V staged into smem (reusing dead sQ/sK region);
// PV via mma reading both operands from smem.
// smem: Q[64][36] + K[128][36] + P[64][132] tf32 = 61440 B -> 3 CTAs/SM
// =====================================================================
#define ATTN_SMEM_BYTES ((64 * 36 + 128 * 36 + 64 * 132) * 4)

__global__ __launch_bounds__(128, 3) void attn_mma_kernel()
{
    extern __shared__ uint32_t smx[];
    uint32_t* sQ = smx;                       // [64][36]
    uint32_t* sK = smx + 64 * 36;             // [128][36]
    uint32_t* sV = smx;                       // [128][36] (reuses sQ+sK after QK^T)
    uint32_t* sP = smx + 64 * 36 + 128 * 36;  // [64][132]

    const int bid = blockIdx.x;
    const int b  = bid >> 4;
    const int h  = (bid >> 1) & 7;
    const int q0 = (bid & 1) * 64;

    const int tid = threadIdx.x;
    const int lane = tid & 31, w = tid >> 5;
    const int g = lane >> 2, t = lane & 3;

    const float* Qg = g_Q + ((size_t)(b * NPG + q0)) * HID + h * HDIM;
    const float* Kg = g_K + ((size_t)b * NPG) * HID + h * HDIM;
    const float* Vg = g_V + ((size_t)b * NPG) * HID + h * HDIM;

    // ---- load Q (64x32) and K (128x32) as tf32 into smem ----
#pragma unroll
    for (int i = 0; i < 4; i++) {
        int f = tid + i * 128;
        int row = f >> 3, cv = (f & 7) * 4;
        float4 v = *(const float4*)&Qg[(size_t)row * HID + cv];
        uint4 u = make_uint4(f2tf(v.x), f2tf(v.y), f2tf(v.z), f2tf(v.w));
        *(uint4*)&sQ[row * 36 + cv] = u;
    }
#pragma unroll
    for (int i = 0; i < 8; i++) {
        int f = tid + i * 128;
        int row = f >> 3, cv = (f & 7) * 4;
        float4 v = *(const float4*)&Kg[(size_t)row * HID + cv];
        uint4 u = make_uint4(f2tf(v.x), f2tf(v.y), f2tf(v.z), f2tf(v.w));
        *(uint4*)&sK[row * 36 + cv] = u;
    }
    __syncthreads();

    const int r = w * 16 + g;   // this thread's base q-row (CTA-local)

    // ---- QK^T : S strip 16x128 per warp, in fragments ----
    uint32_t af[4][4];
#pragma unroll
    for (int ks = 0; ks < 4; ks++) {
        af[ks][0] = sQ[r * 36 + ks * 8 + t];
        af[ks][1] = sQ[(r + 8) * 36 + ks * 8 + t];
        af[ks][2] = sQ[r * 36 + ks * 8 + t + 4];
        af[ks][3] = sQ[(r + 8) * 36 + ks * 8 + t + 4];
    }

    float acc[16][4];
#pragma unroll
    for (int j = 0; j < 16; j++)
        acc[j][0] = acc[j][1] = acc[j][2] = acc[j][3] = 0.f;

#pragma unroll
    for (int j = 0; j < 16; j++) {
        int c = j * 8 + g;
#pragma unroll
        for (int ks = 0; ks < 4; ks++) {
            uint32_t bf[2];
            bf[0] = sK[c * 36 + ks * 8 + t];
            bf[1] = sK[c * 36 + ks * 8 + t + 4];
            mma_tf32(acc[j], af[ks], bf);
        }
    }

    // ---- add bias (head-major, coalesced float2 reads) ----
    const float* bg = g_bias + ((size_t)(b * NHEAD + h) * NPG + q0 + w * 16) * NPG;
#pragma unroll
    for (int j = 0; j < 16; j++) {
        float2 b0 = *(const float2*)&bg[g * NPG + j * 8 + 2 * t];
        float2 b1 = *(const float2*)&bg[(g + 8) * NPG + j * 8 + 2 * t];
        acc[j][0] += b0.x; acc[j][1] += b0.y;
        acc[j][2] += b1.x; acc[j][3] += b1.y;
    }

    // ---- softmax on fragments (rows g and g+8; 4 lanes per row) ----
    float m1 = -1e30f, m2 = -1e30f;
#pragma unroll
    for (int j = 0; j < 16; j++) {
        m1 = fmaxf(m1, fmaxf(acc[j][0], acc[j][1]));
        m2 = fmaxf(m2, fmaxf(acc[j][2], acc[j][3]));
    }
    m1 = fmaxf(m1, __shfl_xor_sync(0xffffffffu, m1, 1));
    m1 = fmaxf(m1, __shfl_xor_sync(0xffffffffu, m1, 2));
    m2 = fmaxf(m2, __shfl_xor_sync(0xffffffffu, m2, 1));
    m2 = fmaxf(m2, __shfl_xor_sync(0xffffffffu, m2, 2));

    float s1 = 0.f, s2 = 0.f;
#pragma unroll
    for (int j = 0; j < 16; j++) {
        acc[j][0] = __expf(acc[j][0] - m1);
        acc[j][1] = __expf(acc[j][1] - m1);
        acc[j][2] = __expf(acc[j][2] - m2);
        acc[j][3] = __expf(acc[j][3] - m2);
        s1 += acc[j][0] + acc[j][1];
        s2 += acc[j][2] + acc[j][3];
    }
    s1 += __shfl_xor_sync(0xffffffffu, s1, 1);
    s1 += __shfl_xor_sync(0xffffffffu, s1, 2);
    s2 += __shfl_xor_sync(0xffffffffu, s2, 1);
    s2 += __shfl_xor_sync(0xffffffffu, s2, 2);
    const float inv1 = 1.0f / s1, inv2 = 1.0f / s2;

    // ---- all warps done reading sQ/sK: repurpose that region for V ----
    __syncthreads();

    // P -> smem (tf32), warp-private strip
#pragma unroll
    for (int j = 0; j < 16; j++) {
        uint2 p0 = make_uint2(f2tf(acc[j][0] * inv1), f2tf(acc[j][1] * inv1));
        uint2 p1 = make_uint2(f2tf(acc[j][2] * inv2), f2tf(acc[j][3] * inv2));
        *(uint2*)&sP[r * 132 + j * 8 + 2 * t] = p0;
        *(uint2*)&sP[(r + 8) * 132 + j * 8 + 2 * t] = p1;
    }

    // V (128x32) -> smem as tf32 (overwrites sQ/sK region)
#pragma unroll
    for (int i = 0; i < 8; i++) {
        int f = tid + i * 128;
        int row = f >> 3, cv = (f & 7) * 4;
        float4 v = *(const float4*)&Vg[(size_t)row * HID + cv];
        uint4 u = make_uint4(f2tf(v.x), f2tf(v.y), f2tf(v.z), f2tf(v.w));
        *(uint4*)&sV[row * 36 + cv] = u;
    }
    __syncthreads();

    // ---- O = P @ V via mma (both operands from smem) ----
    float o[4][4] = {};
#pragma unroll
    for (int ks = 0; ks < 16; ks++) {
        uint32_t pf[4];
        pf[0] = sP[r * 132 + ks * 8 + t];
        pf[1] = sP[(r + 8) * 132 + ks * 8 + t];
        pf[2] = sP[r * 132 + ks * 8 + t + 4];
        pf[3] = sP[(r + 8) * 132 + ks * 8 + t + 4];
#pragma unroll
        for (int nt = 0; nt < 4; nt++) {
            uint32_t bf[2];
            bf[0] = sV[(ks * 8 + t) * 36 + nt * 8 + g];
            bf[1] = sV[(ks * 8 + t + 4) * 36 + nt * 8 + g];
            mma_tf32(o[nt], pf, bf);
        }
    }

    // ---- store O ----
    float* Og = g_A + ((size_t)(b * NPG + q0 + w * 16)) * HID + h * HDIM;
#pragma unroll
    for (int nt = 0; nt < 4; nt++) {
        int col = nt * 8 + 2 * t;
        *(float2*)&Og[(size_t)g * HID + col] = make_float2(o[nt][0], o[nt][1]);
        *(float2*)&Og[(size_t)(g + 8) * HID + col] = make_float2(o[nt][2], o[nt][3]);
    }
}

// =====================================================================
// launch
// =====================================================================
extern "C" void kernel_launch(void* const* d_in, const int* in_sizes, int n_in,
                              void* d_out, int out_size)
{
    const float* x          = (const float*)d_in[0];
    const float* edge_attr  = (const float*)d_in[1];
    const float* Wq         = (const float*)d_in[2];
    const float* bq         = (const float*)d_in[3];
    const float* Wk         = (const float*)d_in[4];
    const float* bk         = (const float*)d_in[5];
    const float* Wv         = (const float*)d_in[6];
    const float* bv         = (const float*)d_in[7];
    const float* Wo         = (const float*)d_in[8];
    const float* bo         = (const float*)d_in[9];
    const float* gate_table = (const float*)d_in[10];
    const float* We         = (const float*)d_in[11];
    const float* be         = (const float*)d_in[12];
    const int*   edge_index = (const int*)d_in[13];
    const int*   gate_type  = (const int*)d_in[14];
    float*       out        = (float*)d_out;

    float* Ap;
    cudaGetSymbolAddress((void**)&Ap, g_A);

    cudaFuncSetAttribute(attn_mma_kernel, cudaFuncAttributeMaxDynamicSharedMemorySize,
                         ATTN_SMEM_BYTES);

    // bias chain: zero -> vectorized scatter -> transpose to head-major
    zero_bias_kernel<<<BIAS_ELEMS / 4 / 256, 256>>>();
    edge_bias_kernel<<<N_EDGE / 256, 256>>>(edge_attr, edge_index, gate_type,
                                            gate_table, We, be);
    transpose_bias_kernel<<<N_GRAPH * NPG / 2, 256>>>();

    dim3 gqkv(HID / 64, N_NODES / 128, 3);   // (4, 256, 3)
    gemm_tf32_qkv_kernel<<<gqkv, 256>>>(x, Wq, bq, Wk, bk, Wv, bv);

    attn_mma_kernel<<<N_GRAPH * NHEAD * 2, 128, ATTN_SMEM_BYTES>>>();

    dim3 go(HID / 64, N_NODES / 128);        // (4, 256)
    gemm_tf32_kernel<<<go, 256>>>(Ap, Wo, bo, out, 1.0f);
}